// round 12
// baseline (speedup 1.0000x reference)
#include <cuda_runtime.h>
#include <cuda_bf16.h>
#include <cstdint>

#define BINS 32
#define CZ   128
#define NCLS 66              // 2*BINS + 2
#define LSEQ 768
#define NB   2
#define TPB  1024            // 32 warps, one CTA per SM
#define NCTAS 148
#define JCHUNK 96            // j-vectors per chunk = 96*512B = 48KB
#define CHUNK_FLOATS (JCHUNK * CZ)             // 12288 floats
#define CHUNK_BYTES  (CHUNK_FLOATS * 4)        // 49152
#define NCHUNK (NB * LSEQ * (LSEQ / JCHUNK))   // 12288
#define NBUF 3               // triple-buffered staging

// dynamic smem layout (bytes):
//   [0, 33792)             wb  (66*128 floats; row 0 = zeros = mask sink)
//   [33792, +3*48KB)       stage[3] triple buffer
//   then rj (1536 ints), mj (1536 bytes)
#define OFF_WB    0
#define OFF_STAGE 33792
#define OFF_RJ    (OFF_STAGE + NBUF * CHUNK_BYTES)
#define OFF_MJ    (OFF_RJ + NB * LSEQ * 4)
#define SMEM_TOTAL (OFF_MJ + NB * LSEQ)        // 188928 B

// Triple-buffered bulk-store kernel: compute each 48KB chunk into a smem
// staging buffer, push it with ONE cp.async.bulk so the DRAM controller sees
// whole-chunk burst descriptors. wait_group.read 2 keeps up to 3 chunks of
// writes in flight so the TMA queue never runs dry during compute+barrier.
__global__ __launch_bounds__(TPB) void relpos_kernel(
    const int*   __restrict__ ridx,
    const int*   __restrict__ rmask,
    const float* __restrict__ W,
    const float* __restrict__ bias,
    float*       __restrict__ out)
{
    extern __shared__ char smem[];
    float*         wb    = reinterpret_cast<float*>(smem + OFF_WB);
    float*         stage = reinterpret_cast<float*>(smem + OFF_STAGE);
    int*           rj    = reinterpret_cast<int*>(smem + OFF_RJ);
    unsigned char* mj    = reinterpret_cast<unsigned char*>(smem + OFF_MJ);

    const int tid = threadIdx.x;

    #pragma unroll 2
    for (int k = tid; k < NCLS * CZ; k += TPB)
        wb[k] = (k < CZ) ? 0.0f : (W[k] + bias[k & (CZ - 1)]);

    for (int k = tid; k < NB * LSEQ; k += TPB) {
        rj[k] = ridx[k];
        mj[k] = (unsigned char)(rmask[k] != 0);
    }
    __syncthreads();

    const int lane = tid & 31;
    const int warp = tid >> 5;

    uint32_t stage_u32;
    asm("{ .reg .u64 t; cvta.to.shared.u64 t, %1; cvt.u32.u64 %0, t; }"
        : "=r"(stage_u32) : "l"(stage));

    int it = 0;
    int buf = 0;
    for (int c = blockIdx.x; c < NCHUNK; c += NCTAS, it++) {
        float4* sbuf = reinterpret_cast<float4*>(stage + buf * CHUNK_FLOATS);

        // Before overwriting this buffer, ensure the bulk store issued NBUF
        // iterations ago (which read it) has finished its smem reads.
        if (it >= NBUF && tid == 0)
            asm volatile("cp.async.bulk.wait_group.read %0;" :: "n"(NBUF - 1)
                         : "memory");
        __syncthreads();

        const int row   = c >> 3;
        const int jbase = (c & 7) * JCHUNK;
        const int b     = row / LSEQ;
        const int i     = row - b * LSEQ;
        const int boff  = b * LSEQ;
        const int ri    = rj[boff + i];
        const bool mi   = (mj[boff + i] != 0);

        // 96 j's / 32 warps = 3 per warp; write into staging buffer
        #pragma unroll 3
        for (int t = warp; t < JCHUNK; t += TPB / 32) {
            const int j = jbase + t;
            int d = rj[boff + j] - ri;
            d = min(max(d, -BINS), BINS) + BINS + 1;      // [1, 65]
            if (!(mi && (mj[boff + j] != 0))) d = 0;      // masked -> zero row
            float4 v = *reinterpret_cast<const float4*>(&wb[d * CZ + lane * 4]);
            sbuf[t * 32 + lane] = v;
        }
        __syncthreads();

        if (tid == 0) {
            asm volatile("fence.proxy.async.shared::cta;" ::: "memory");
            const float* dst = out + (size_t)row * LSEQ * CZ + (size_t)jbase * CZ;
            asm volatile(
                "cp.async.bulk.global.shared::cta.bulk_group [%0], [%1], %2;"
                :: "l"(dst), "r"(stage_u32 + buf * CHUNK_BYTES), "n"(CHUNK_BYTES)
                : "memory");
            asm volatile("cp.async.bulk.commit_group;" ::: "memory");
        }

        buf = (buf == NBUF - 1) ? 0 : buf + 1;
    }

    // Drain all outstanding bulk stores before exit.
    if (tid == 0)
        asm volatile("cp.async.bulk.wait_group 0;" ::: "memory");
}

extern "C" void kernel_launch(void* const* d_in, const int* in_sizes, int n_in,
                              void* d_out, int out_size) {
    const int*   ridx  = (const int*)d_in[0];
    const int*   rmask = (const int*)d_in[1];
    const float* W     = (const float*)d_in[2];
    const float* bias  = (const float*)d_in[3];
    float*       out   = (float*)d_out;

    static int configured = 0;
    if (!configured) {
        cudaFuncSetAttribute(relpos_kernel,
                             cudaFuncAttributeMaxDynamicSharedMemorySize,
                             SMEM_TOTAL);
        configured = 1;
    }
    relpos_kernel<<<NCTAS, TPB, SMEM_TOTAL>>>(ridx, rmask, W, bias, out);
}

// round 13
// speedup vs baseline: 1.3984x; 1.3984x over previous
#include <cuda_runtime.h>
#include <cuda_bf16.h>
#include <cstdint>

#define BINS 32
#define CZ   128
#define NCLS 66              // 2*BINS + 2
#define LSEQ 768
#define NB   2
#define TPB  1024            // 32 warps, one CTA per SM
#define NCTAS 148
#define JCHUNK 128           // j-vectors per chunk = 128*512B = 64KB
#define CPR   (LSEQ / JCHUNK)                  // 6 chunks per row
#define CHUNK_FLOATS (JCHUNK * CZ)             // 16384 floats
#define CHUNK_BYTES  (CHUNK_FLOATS * 4)        // 65536
#define NCHUNK (NB * LSEQ * CPR)               // 9216
#define NBUF 2               // double buffer: exactly 1 drain overlaps compute

// dynamic smem layout (bytes):
//   [0, 33792)             wb  (66*128 floats; row 0 = zeros = mask sink)
//   [33792, +2*64KB)       stage[2] double buffer
//   then rj (1536 ints), mj (1536 bytes)
#define OFF_WB    0
#define OFF_STAGE 33792
#define OFF_RJ    (OFF_STAGE + NBUF * CHUNK_BYTES)
#define OFF_MJ    (OFF_RJ + NB * LSEQ * 4)
#define SMEM_TOTAL (OFF_MJ + NB * LSEQ)        // 172544 B

// Double-buffered bulk-store kernel, 64KB chunks. Compute each chunk into a
// smem staging buffer, push with ONE cp.async.bulk so the DRAM controller
// sees whole-chunk burst descriptors. NBUF=2 keeps exactly one TMA smem-read
// drain concurrent with compute (NBUF=3 measured -40%: smem port contention).
__global__ __launch_bounds__(TPB) void relpos_kernel(
    const int*   __restrict__ ridx,
    const int*   __restrict__ rmask,
    const float* __restrict__ W,
    const float* __restrict__ bias,
    float*       __restrict__ out)
{
    extern __shared__ char smem[];
    float*         wb    = reinterpret_cast<float*>(smem + OFF_WB);
    float*         stage = reinterpret_cast<float*>(smem + OFF_STAGE);
    int*           rj    = reinterpret_cast<int*>(smem + OFF_RJ);
    unsigned char* mj    = reinterpret_cast<unsigned char*>(smem + OFF_MJ);

    const int tid = threadIdx.x;

    #pragma unroll 2
    for (int k = tid; k < NCLS * CZ; k += TPB)
        wb[k] = (k < CZ) ? 0.0f : (W[k] + bias[k & (CZ - 1)]);

    for (int k = tid; k < NB * LSEQ; k += TPB) {
        rj[k] = ridx[k];
        mj[k] = (unsigned char)(rmask[k] != 0);
    }
    __syncthreads();

    const int lane = tid & 31;
    const int warp = tid >> 5;

    uint32_t stage_u32;
    asm("{ .reg .u64 t; cvta.to.shared.u64 t, %1; cvt.u32.u64 %0, t; }"
        : "=r"(stage_u32) : "l"(stage));

    int it = 0;
    for (int c = blockIdx.x; c < NCHUNK; c += NCTAS, it++) {
        const int buf = it & 1;
        float4* sbuf = reinterpret_cast<float4*>(stage + buf * CHUNK_FLOATS);

        // Before overwriting this buffer, ensure the bulk store issued two
        // iterations ago (which read it) has finished its smem reads.
        if (it >= NBUF && tid == 0)
            asm volatile("cp.async.bulk.wait_group.read %0;" :: "n"(NBUF - 1)
                         : "memory");
        __syncthreads();

        const int row   = c / CPR;              // 0 .. B*L-1
        const int jbase = (c - row * CPR) * JCHUNK;
        const int b     = row / LSEQ;
        const int i     = row - b * LSEQ;
        const int boff  = b * LSEQ;
        const int ri    = rj[boff + i];
        const bool mi   = (mj[boff + i] != 0);

        // 128 j's / 32 warps = 4 per warp; write into staging buffer
        #pragma unroll 4
        for (int t = warp; t < JCHUNK; t += TPB / 32) {
            const int j = jbase + t;
            int d = rj[boff + j] - ri;
            d = min(max(d, -BINS), BINS) + BINS + 1;      // [1, 65]
            if (!(mi && (mj[boff + j] != 0))) d = 0;      // masked -> zero row
            float4 v = *reinterpret_cast<const float4*>(&wb[d * CZ + lane * 4]);
            sbuf[t * 32 + lane] = v;
        }
        __syncthreads();

        if (tid == 0) {
            asm volatile("fence.proxy.async.shared::cta;" ::: "memory");
            const float* dst = out + (size_t)row * LSEQ * CZ + (size_t)jbase * CZ;
            asm volatile(
                "cp.async.bulk.global.shared::cta.bulk_group [%0], [%1], %2;"
                :: "l"(dst), "r"(stage_u32 + buf * CHUNK_BYTES), "n"(CHUNK_BYTES)
                : "memory");
            asm volatile("cp.async.bulk.commit_group;" ::: "memory");
        }
    }

    // Drain all outstanding bulk stores before exit.
    if (tid == 0)
        asm volatile("cp.async.bulk.wait_group 0;" ::: "memory");
}

extern "C" void kernel_launch(void* const* d_in, const int* in_sizes, int n_in,
                              void* d_out, int out_size) {
    const int*   ridx  = (const int*)d_in[0];
    const int*   rmask = (const int*)d_in[1];
    const float* W     = (const float*)d_in[2];
    const float* bias  = (const float*)d_in[3];
    float*       out   = (float*)d_out;

    static int configured = 0;
    if (!configured) {
        cudaFuncSetAttribute(relpos_kernel,
                             cudaFuncAttributeMaxDynamicSharedMemorySize,
                             SMEM_TOTAL);
        configured = 1;
    }
    relpos_kernel<<<NCTAS, TPB, SMEM_TOTAL>>>(ridx, rmask, W, bias, out);
}

// round 14
// speedup vs baseline: 1.5506x; 1.1088x over previous
#include <cuda_runtime.h>
#include <cuda_bf16.h>
#include <cstdint>

#define BINS 32
#define CZ   128
#define NCLS 66              // 2*BINS + 2
#define LSEQ 768
#define NB   2
#define TPB  1024            // 32 warps, one CTA per SM
#define NCTAS 148
#define JCHUNK 64            // j-vectors per chunk = 64*512B = 32KB
#define CPR   (LSEQ / JCHUNK)                  // 12 chunks per row
#define CHUNK_FLOATS (JCHUNK * CZ)             // 8192 floats
#define CHUNK_BYTES  (CHUNK_FLOATS * 4)        // 32768
#define NCHUNK (NB * LSEQ * CPR)               // 18432
#define NBUF 2               // double buffer: exactly 1 drain overlaps compute

// dynamic smem layout (bytes):
//   [0, 33792)             wb  (66*128 floats; row 0 = zeros = mask sink)
//   [33792, +2*32KB)       stage[2] double buffer
//   then rj (1536 ints), mj (1536 bytes)
#define OFF_WB    0
#define OFF_STAGE 33792
#define OFF_RJ    (OFF_STAGE + NBUF * CHUNK_BYTES)
#define OFF_MJ    (OFF_RJ + NB * LSEQ * 4)
#define SMEM_TOTAL (OFF_MJ + NB * LSEQ)        // ~107KB

// Double-buffered bulk-store kernel, 32KB chunks. Chunk-size scan: 64KB=95.5us,
// 48KB=90.8us (profiled) -> finer chunks shrink the serial barrier quantum and
// keep the TMA write queue fed. NBUF=2 keeps exactly one TMA smem-read drain
// concurrent with compute (NBUF=3 measured -40%: smem port contention).
__global__ __launch_bounds__(TPB) void relpos_kernel(
    const int*   __restrict__ ridx,
    const int*   __restrict__ rmask,
    const float* __restrict__ W,
    const float* __restrict__ bias,
    float*       __restrict__ out)
{
    extern __shared__ char smem[];
    float*         wb    = reinterpret_cast<float*>(smem + OFF_WB);
    float*         stage = reinterpret_cast<float*>(smem + OFF_STAGE);
    int*           rj    = reinterpret_cast<int*>(smem + OFF_RJ);
    unsigned char* mj    = reinterpret_cast<unsigned char*>(smem + OFF_MJ);

    const int tid = threadIdx.x;

    #pragma unroll 2
    for (int k = tid; k < NCLS * CZ; k += TPB)
        wb[k] = (k < CZ) ? 0.0f : (W[k] + bias[k & (CZ - 1)]);

    for (int k = tid; k < NB * LSEQ; k += TPB) {
        rj[k] = ridx[k];
        mj[k] = (unsigned char)(rmask[k] != 0);
    }
    __syncthreads();

    const int lane = tid & 31;
    const int warp = tid >> 5;

    uint32_t stage_u32;
    asm("{ .reg .u64 t; cvta.to.shared.u64 t, %1; cvt.u32.u64 %0, t; }"
        : "=r"(stage_u32) : "l"(stage));

    int it = 0;
    for (int c = blockIdx.x; c < NCHUNK; c += NCTAS, it++) {
        const int buf = it & 1;
        float4* sbuf = reinterpret_cast<float4*>(stage + buf * CHUNK_FLOATS);

        // Before overwriting this buffer, ensure the bulk store issued two
        // iterations ago (which read it) has finished its smem reads.
        if (it >= NBUF && tid == 0)
            asm volatile("cp.async.bulk.wait_group.read %0;" :: "n"(NBUF - 1)
                         : "memory");
        __syncthreads();

        const int row   = c / CPR;              // 0 .. B*L-1
        const int jbase = (c - row * CPR) * JCHUNK;
        const int b     = row / LSEQ;
        const int i     = row - b * LSEQ;
        const int boff  = b * LSEQ;
        const int ri    = rj[boff + i];
        const bool mi   = (mj[boff + i] != 0);

        // 64 j's / 32 warps = 2 per warp; write into staging buffer
        #pragma unroll 2
        for (int t = warp; t < JCHUNK; t += TPB / 32) {
            const int j = jbase + t;
            int d = rj[boff + j] - ri;
            d = min(max(d, -BINS), BINS) + BINS + 1;      // [1, 65]
            if (!(mi && (mj[boff + j] != 0))) d = 0;      // masked -> zero row
            float4 v = *reinterpret_cast<const float4*>(&wb[d * CZ + lane * 4]);
            sbuf[t * 32 + lane] = v;
        }
        __syncthreads();

        if (tid == 0) {
            asm volatile("fence.proxy.async.shared::cta;" ::: "memory");
            const float* dst = out + (size_t)row * LSEQ * CZ + (size_t)jbase * CZ;
            asm volatile(
                "cp.async.bulk.global.shared::cta.bulk_group [%0], [%1], %2;"
                :: "l"(dst), "r"(stage_u32 + buf * CHUNK_BYTES), "n"(CHUNK_BYTES)
                : "memory");
            asm volatile("cp.async.bulk.commit_group;" ::: "memory");
        }
    }

    // Drain all outstanding bulk stores before exit.
    if (tid == 0)
        asm volatile("cp.async.bulk.wait_group 0;" ::: "memory");
}

extern "C" void kernel_launch(void* const* d_in, const int* in_sizes, int n_in,
                              void* d_out, int out_size) {
    const int*   ridx  = (const int*)d_in[0];
    const int*   rmask = (const int*)d_in[1];
    const float* W     = (const float*)d_in[2];
    const float* bias  = (const float*)d_in[3];
    float*       out   = (float*)d_out;

    static int configured = 0;
    if (!configured) {
        cudaFuncSetAttribute(relpos_kernel,
                             cudaFuncAttributeMaxDynamicSharedMemorySize,
                             SMEM_TOTAL);
        configured = 1;
    }
    relpos_kernel<<<NCTAS, TPB, SMEM_TOTAL>>>(ridx, rmask, W, bias, out);
}